// round 9
// baseline (speedup 1.0000x reference)
#include <cuda_runtime.h>
#include <cuda_bf16.h>
#include <mma.h>
#include <math.h>
#include <stdint.h>

using namespace nvcuda;

// ---------------- problem constants ----------------
constexpr int NN  = 50000;
constexpr int EE  = 800000;
constexpr int HD  = 256;
constexpr int BB  = 256;
constexpr int ND  = 5000;
constexpr int KK  = 16;
constexpr int ER  = 20000;

// ---------------- device scratch (no allocs allowed) ----------------
__device__ __align__(16) float g_h[(size_t)NN * HD];
__device__ __align__(16) float g_emb[(size_t)NN * HD];
__device__ __align__(16) __nv_bfloat16 g_xhi[(size_t)NN * HD];
__device__ __align__(16) __nv_bfloat16 g_xlo[(size_t)NN * HD];
__device__ __align__(16) __nv_bfloat16 g_acthi[(size_t)NN * HD];
__device__ __align__(16) __nv_bfloat16 g_actlo[(size_t)NN * HD];
__device__ __align__(16) __nv_bfloat16 g_w1hi[256 * 256];
__device__ __align__(16) __nv_bfloat16 g_w1lo[256 * 256];
__device__ __align__(16) __nv_bfloat16 g_w2hi[256 * 256];
__device__ __align__(16) __nv_bfloat16 g_w2lo[256 * 256];
__device__ float g_ssrc[NN];
__device__ float g_sdst[NN];
__device__ int   g_deg[NN];
__device__ int   g_cursor[NN];
__device__ int   g_rowptr[NN + 1];
__device__ int   g_csr_src[EE];
__device__ int   g_cnt[3 * ND];

constexpr int PB = 128;
constexpr int CHUNK = (NN + PB - 1) / PB;  // 391
__device__ int g_part[PB];

// ---------------- helpers ----------------
__device__ __forceinline__ uint32_t smem_u32(const void* p) {
    uint32_t a;
    asm("{ .reg .u64 t; cvta.to.shared.u64 t, %1; cvt.u32.u64 %0, t; }" : "=r"(a) : "l"(p));
    return a;
}
__device__ __forceinline__ void cp16(uint32_t dst, const void* src) {
    asm volatile("cp.async.cg.shared.global [%0], [%1], 16;" :: "r"(dst), "l"(src));
}

// ---------------- fused prep: zero + x split + W1/W2 splits ---------------------
__global__ void prep_all_kernel(const float* __restrict__ x,
                                const float* __restrict__ W1,
                                const float* __restrict__ W2) {
    int i = blockIdx.x * blockDim.x + threadIdx.x;
    if (i < NN * HD) {
        float v = x[i];
        __nv_bfloat16 h = __float2bfloat16(v);
        g_xhi[i] = h;
        g_xlo[i] = __float2bfloat16(v - __bfloat162float(h));
    }
    if (i < 256 * 256) {
        float v1 = W1[i];
        __nv_bfloat16 h1 = __float2bfloat16(v1);
        g_w1hi[i] = h1;
        g_w1lo[i] = __float2bfloat16(v1 - __bfloat162float(h1));
        float v2 = W2[i];
        __nv_bfloat16 h2 = __float2bfloat16(v2);
        g_w2hi[i] = h2;
        g_w2lo[i] = __float2bfloat16(v2 - __bfloat162float(h2));
    }
    if (i < NN) { g_deg[i] = 0; g_cursor[i] = 0; }
    if (i < 3 * ND) g_cnt[i] = 0;
    if (i == 0) g_rowptr[NN] = EE;
}

// ---------------- fused histograms ----------------
__global__ void hist_kernel(const int* __restrict__ dst, const int* __restrict__ res) {
    int e = blockIdx.x * blockDim.x + threadIdx.x;
    if (e < EE) atomicAdd(&g_deg[dst[e]], 1);
    if (e < 3 * ER) atomicAdd(&g_cnt[(e / ER) * ND + res[e]], 1);
}

__global__ void partial_kernel() {
    __shared__ int sh[256];
    int b = blockIdx.x, t = threadIdx.x;
    int base = b * CHUNK;
    int s = 0;
    for (int i = t; i < CHUNK; i += 256) {
        int idx = base + i;
        if (idx < NN) s += g_deg[idx];
    }
    sh[t] = s;
    __syncthreads();
    for (int off = 128; off; off >>= 1) {
        if (t < off) sh[t] += sh[t + off];
        __syncthreads();
    }
    if (t == 0) g_part[b] = sh[0];
}

__global__ void rowptr_kernel() {
    __shared__ int red[128];
    __shared__ int s[512];
    int b = blockIdx.x, t = threadIdx.x;
    if (t < 128) red[t] = (t < b) ? g_part[t] : 0;
    __syncthreads();
    for (int off = 64; off; off >>= 1) {
        if (t < off) red[t] += red[t + off];
        __syncthreads();
    }
    int base = red[0];
    int idx = b * CHUNK + t;
    int v = (t < CHUNK && idx < NN) ? g_deg[idx] : 0;
    s[t] = v;
    __syncthreads();
    for (int off = 1; off < 512; off <<= 1) {
        int u = (t >= off) ? s[t - off] : 0;
        __syncthreads();
        s[t] += u;
        __syncthreads();
    }
    if (t < CHUNK && idx < NN) g_rowptr[idx] = base + s[t] - v;
}

__global__ void scatter_kernel(const int* __restrict__ src, const int* __restrict__ dst) {
    int e = blockIdx.x * blockDim.x + threadIdx.x;
    if (e < EE) {
        int d = dst[e];
        int pos = atomicAdd(&g_cursor[d], 1);
        g_csr_src[g_rowptr[d] + pos] = src[e];
    }
}

// ---------------- WMMA bf16 GEMM, 3xBF16, cp.async double-buffered --------------
constexpr int BM = 128, BN = 128, KC = 32;
constexpr int LDA = KC + 8;
constexpr int LDB = BN + 8;
constexpr int SZ_A = BM * LDA * 2;
constexpr int SZ_B = KC * LDB * 2;
constexpr int OFF_AH = 0;
constexpr int OFF_AL = SZ_A;
constexpr int OFF_BH = 2 * SZ_A;
constexpr int OFF_BL = 2 * SZ_A + SZ_B;
constexpr int BUF = 2 * SZ_A + 2 * SZ_B;
constexpr int SMEM_GEMM = 2 * BUF;

template <int LAYER>
__global__ __launch_bounds__(256, 2) void gemm_tc(int M) {
    const __nv_bfloat16* __restrict__ Ahi = (LAYER == 1) ? g_xhi : g_acthi;
    const __nv_bfloat16* __restrict__ Alo = (LAYER == 1) ? g_xlo : g_actlo;
    const __nv_bfloat16* __restrict__ Whi = (LAYER == 1) ? g_w1hi : g_w2hi;
    const __nv_bfloat16* __restrict__ Wlo = (LAYER == 1) ? g_w1lo : g_w2lo;

    extern __shared__ char smem[];
    uint32_t sb = smem_u32(smem);

    int tid = threadIdx.x;
    int wid = tid >> 5;
    int wm = wid & 3;
    int wn = wid >> 2;
    int row0 = blockIdx.x * BM;
    int col0 = blockIdx.y * BN;

    wmma::fragment<wmma::accumulator, 16, 16, 16, float> acc[2][4];
#pragma unroll
    for (int mt = 0; mt < 2; mt++)
#pragma unroll
        for (int nt = 0; nt < 4; nt++) wmma::fill_fragment(acc[mt][nt], 0.0f);

    auto load_chunk = [&](int c) {
        int kc = c * KC;
        uint32_t bb = sb + (c & 1) * BUF;
#pragma unroll
        for (int p = 0; p < 2; p++) {
            int t = p * 256 + tid;
            int r = t >> 2, seg = t & 3;
            int gr = row0 + r; if (gr >= M) gr = M - 1;
            size_t go = (size_t)gr * 256 + kc + seg * 8;
            uint32_t so = r * (LDA * 2) + seg * 16;
            cp16(bb + OFF_AH + so, Ahi + go);
            cp16(bb + OFF_AL + so, Alo + go);
        }
#pragma unroll
        for (int p = 0; p < 2; p++) {
            int t = p * 256 + tid;
            int k = t >> 4, seg = t & 15;
            size_t go = (size_t)(kc + k) * 256 + col0 + seg * 8;
            uint32_t so = k * (LDB * 2) + seg * 16;
            cp16(bb + OFF_BH + so, Whi + go);
            cp16(bb + OFF_BL + so, Wlo + go);
        }
        asm volatile("cp.async.commit_group;" ::: "memory");
    };

    load_chunk(0);

    for (int c = 0; c < 8; c++) {
        if (c < 7) {
            load_chunk(c + 1);
            asm volatile("cp.async.wait_group 1;" ::: "memory");
        } else {
            asm volatile("cp.async.wait_group 0;" ::: "memory");
        }
        __syncthreads();

        const char* buf = smem + (c & 1) * BUF;
        const __nv_bfloat16* bAh = (const __nv_bfloat16*)(buf + OFF_AH);
        const __nv_bfloat16* bAl = (const __nv_bfloat16*)(buf + OFF_AL);
        const __nv_bfloat16* bBh = (const __nv_bfloat16*)(buf + OFF_BH);
        const __nv_bfloat16* bBl = (const __nv_bfloat16*)(buf + OFF_BL);

#pragma unroll
        for (int s = 0; s < KC / 16; s++) {
            wmma::fragment<wmma::matrix_a, 16, 16, 16, __nv_bfloat16, wmma::row_major> ah[2], al[2];
#pragma unroll
            for (int mt = 0; mt < 2; mt++) {
                wmma::load_matrix_sync(ah[mt], bAh + (wm * 32 + mt * 16) * LDA + s * 16, LDA);
                wmma::load_matrix_sync(al[mt], bAl + (wm * 32 + mt * 16) * LDA + s * 16, LDA);
            }
#pragma unroll
            for (int nt = 0; nt < 4; nt++) {
                wmma::fragment<wmma::matrix_b, 16, 16, 16, __nv_bfloat16, wmma::row_major> bh, bl;
                wmma::load_matrix_sync(bh, bBh + (s * 16) * LDB + wn * 64 + nt * 16, LDB);
                wmma::load_matrix_sync(bl, bBl + (s * 16) * LDB + wn * 64 + nt * 16, LDB);
#pragma unroll
                for (int mt = 0; mt < 2; mt++) {
                    wmma::mma_sync(acc[mt][nt], ah[mt], bh, acc[mt][nt]);
                    wmma::mma_sync(acc[mt][nt], ah[mt], bl, acc[mt][nt]);
                    wmma::mma_sync(acc[mt][nt], al[mt], bh, acc[mt][nt]);
                }
            }
        }
        __syncthreads();
    }

    int mrow = row0 + wm * 32;
    int ncol = col0 + wn * 64;
#pragma unroll
    for (int mt = 0; mt < 2; mt++) {
        int rbase = mrow + mt * 16;
        if (rbase + 16 <= M) {
#pragma unroll
            for (int nt = 0; nt < 4; nt++)
                wmma::store_matrix_sync(g_h + (size_t)rbase * 256 + ncol + nt * 16,
                                        acc[mt][nt], 256, wmma::mem_row_major);
        }
    }
}

// ---------------- per-node attention dot products ----------------
__global__ __launch_bounds__(256) void sdots_kernel(const float* __restrict__ asrc,
                                                    const float* __restrict__ adst) {
    int w = (blockIdx.x * blockDim.x + threadIdx.x) >> 5;
    int lane = threadIdx.x & 31;
    if (w >= NN) return;
    const float4* hp = (const float4*)(g_h + (size_t)w * 256);
    const float4* as4 = (const float4*)asrc;
    const float4* ad4 = (const float4*)adst;
    float4 v0 = hp[lane], v1 = hp[32 + lane];
    float4 a0 = as4[lane], a1 = as4[32 + lane];
    float4 d0 = ad4[lane], d1 = ad4[32 + lane];
    float s1 = v0.x * a0.x + v0.y * a0.y + v0.z * a0.z + v0.w * a0.w
             + v1.x * a1.x + v1.y * a1.y + v1.z * a1.z + v1.w * a1.w;
    float s2 = v0.x * d0.x + v0.y * d0.y + v0.z * d0.z + v0.w * d0.w
             + v1.x * d1.x + v1.y * d1.y + v1.z * d1.z + v1.w * d1.w;
#pragma unroll
    for (int o = 16; o; o >>= 1) {
        s1 += __shfl_xor_sync(0xffffffffu, s1, o);
        s2 += __shfl_xor_sync(0xffffffffu, s2, o);
    }
    if (lane == 0) { g_ssrc[w] = s1; g_sdst[w] = s2; }
}

// ---------------- fused GAT softmax + aggregation, 2 warps per dst ----------------
__device__ __forceinline__ float leaky02(float s) { return s > 0.f ? s : 0.2f * s; }

template <int LAYER>  // LAYER==1: out = act bf16 hi/lo with silu; LAYER==2: out=g_emb
__global__ __launch_bounds__(256) void gat_aggregate_kernel(const float* __restrict__ bias) {
    int gw = (blockIdx.x * blockDim.x + threadIdx.x) >> 5;  // global warp
    int w = gw >> 1;            // destination node
    int half = gw & 1;          // column half: 0 -> cols [0,128), 1 -> [128,256)
    int lane = threadIdx.x & 31;
    if (w >= NN) return;
    int co = half * 32 + lane;  // float4 index within the 256-col row (0..63)

    int base = g_rowptr[w];
    int d = g_rowptr[w + 1] - base;
    float4 acc = make_float4(0.f, 0.f, 0.f, 0.f);

    if (d > 0) {
        float sdv = g_sdst[w];
        // cache first 32 edge logits in registers (one per lane)
        float e = -1e30f;
        if (lane < d) e = leaky02(g_ssrc[g_csr_src[base + lane]] + sdv);
        float mx = e;
        for (int i = 32 + lane; i < d; i += 32)
            mx = fmaxf(mx, leaky02(g_ssrc[g_csr_src[base + i]] + sdv));
#pragma unroll
        for (int o = 16; o; o >>= 1) mx = fmaxf(mx, __shfl_xor_sync(0xffffffffu, mx, o));
        float p = (lane < d) ? __expf(e - mx) : 0.f;
        float z = p;
        for (int i = 32 + lane; i < d; i += 32)
            z += __expf(leaky02(g_ssrc[g_csr_src[base + i]] + sdv) - mx);
#pragma unroll
        for (int o = 16; o; o >>= 1) z += __shfl_xor_sync(0xffffffffu, z, o);
        float invz = 1.f / (z + 1e-16f);
        float pn = p * invz;  // normalized weight for cached edge `lane`

        int dcap = d < 32 ? d : 32;
#pragma unroll 8
        for (int i = 0; i < dcap; i++) {
            float a = __shfl_sync(0xffffffffu, pn, i);
            int src = g_csr_src[base + i];
            float4 v = ((const float4*)(g_h + (size_t)src * 256))[co];
            acc.x += a * v.x; acc.y += a * v.y; acc.z += a * v.z; acc.w += a * v.w;
        }
        for (int i = 32; i < d; i++) {
            int src = g_csr_src[base + i];
            float a = __expf(leaky02(g_ssrc[src] + sdv) - mx) * invz;
            float4 v = ((const float4*)(g_h + (size_t)src * 256))[co];
            acc.x += a * v.x; acc.y += a * v.y; acc.z += a * v.z; acc.w += a * v.w;
        }
    }

    float4 bb = ((const float4*)bias)[co];
    acc.x += bb.x; acc.y += bb.y; acc.z += bb.z; acc.w += bb.w;

    if (LAYER == 1) {
        float v[4] = {acc.x, acc.y, acc.z, acc.w};
#pragma unroll
        for (int j = 0; j < 4; j++) v[j] = v[j] / (1.f + __expf(-v[j]));
        size_t o0 = (size_t)w * 256 + co * 4;
#pragma unroll
        for (int j = 0; j < 4; j++) {
            __nv_bfloat16 h = __float2bfloat16(v[j]);
            g_acthi[o0 + j] = h;
            g_actlo[o0 + j] = __float2bfloat16(v[j] - __bfloat162float(h));
        }
    } else {
        ((float4*)(g_emb + (size_t)w * 256))[co] = acc;
    }
}

// ---------------- sequential per-triplet scan ----------------
__global__ void scan_seq_kernel(const int* __restrict__ head, const int* __restrict__ rel,
                                const int* __restrict__ g2l, const int* __restrict__ nb,
                                const float* __restrict__ wts) {
    int tid = threadIdx.x;
    for (int t = 0; t < BB; t++) {
        int r = rel[t];
        if (r < 4 || r > 6) continue;
        int hi = head[t];
        int local = g2l[hi];
        int ridx = r - 4;
        float deg = (float)g_cnt[ridx * ND + local];
        float c = 0.7f * __expf(-0.7f * deg) + 0.2f;
        float vec = 0.f;
#pragma unroll
        for (int k = 0; k < KK; k++) {
            int n = nb[local * KK + k];
            vec += wts[local * KK + k] * g_emb[(size_t)n * 256 + tid];
        }
        float cur = g_emb[(size_t)hi * 256 + tid];
        g_emb[(size_t)hi * 256 + tid] = c * vec + (1.f - c) * cur;
    }
}

// ---------------- DistMult decode + sigmoid ----------------
__global__ __launch_bounds__(256) void decode_kernel(const int* __restrict__ head,
                                                     const int* __restrict__ rel,
                                                     const int* __restrict__ tail,
                                                     const float* __restrict__ rel_emb,
                                                     float* __restrict__ out) {
    int w = (blockIdx.x * blockDim.x + threadIdx.x) >> 5;
    int lane = threadIdx.x & 31;
    if (w >= BB) return;
    int hi = head[w], ti = tail[w], r = rel[w];
    const float4* hp = (const float4*)(g_emb + (size_t)hi * 256);
    const float4* tp = (const float4*)(g_emb + (size_t)ti * 256);
    const float4* rp = (const float4*)(rel_emb + (size_t)r * 256);
    float4 h0 = hp[lane], h1 = hp[32 + lane];
    float4 t0 = tp[lane], t1 = tp[32 + lane];
    float4 r0 = rp[lane], r1 = rp[32 + lane];
    float s = h0.x * r0.x * t0.x + h0.y * r0.y * t0.y + h0.z * r0.z * t0.z + h0.w * r0.w * t0.w
            + h1.x * r1.x * t1.x + h1.y * r1.y * t1.y + h1.z * r1.z * t1.z + h1.w * r1.w * t1.w;
#pragma unroll
    for (int o = 16; o; o >>= 1) s += __shfl_xor_sync(0xffffffffu, s, o);
    if (lane == 0) out[w] = 1.f / (1.f + __expf(-s));
}

// ---------------- host launch ----------------
extern "C" void kernel_launch(void* const* d_in, const int* in_sizes, int n_in,
                              void* d_out, int out_size) {
    const float* x        = (const float*)d_in[0];
    const int*   eidx     = (const int*)d_in[1];
    const int*   head     = (const int*)d_in[2];
    const int*   rel      = (const int*)d_in[3];
    const int*   tail     = (const int*)d_in[4];
    const int*   g2l      = (const int*)d_in[5];
    const int*   reledge  = (const int*)d_in[6];
    const int*   simnb    = (const int*)d_in[7];
    const float* simw     = (const float*)d_in[8];
    const float* W1       = (const float*)d_in[9];
    const float* a1s      = (const float*)d_in[10];
    const float* a1d      = (const float*)d_in[11];
    const float* b1       = (const float*)d_in[12];
    const float* W2       = (const float*)d_in[13];
    const float* a2s      = (const float*)d_in[14];
    const float* a2d      = (const float*)d_in[15];
    const float* b2       = (const float*)d_in[16];
    const float* rel_emb  = (const float*)d_in[17];
    float* out = (float*)d_out;

    const int* src = eidx;
    const int* dst = eidx + EE;

    cudaFuncSetAttribute(gemm_tc<1>, cudaFuncAttributeMaxDynamicSharedMemorySize, SMEM_GEMM);
    cudaFuncSetAttribute(gemm_tc<2>, cudaFuncAttributeMaxDynamicSharedMemorySize, SMEM_GEMM);

    dim3 ggrid((NN + BM - 1) / BM, 2);
    int nwBlocks = (NN * 32 + 255) / 256;       // warp-per-node kernels
    int aggBlocks = (NN * 64 + 255) / 256;      // 2 warps per node

    prep_all_kernel<<<(NN * HD + 255) / 256, 256>>>(x, W1, W2);    // 0
    hist_kernel<<<(EE + 255) / 256, 256>>>(dst, reledge);          // 1
    partial_kernel<<<PB, 256>>>();                                 // 2
    gemm_tc<1><<<ggrid, 256, SMEM_GEMM>>>(NN);                     // 3  <- profiled
    rowptr_kernel<<<PB, 512>>>();                                  // 4
    scatter_kernel<<<(EE + 255) / 256, 256>>>(src, dst);           // 5
    sdots_kernel<<<nwBlocks, 256>>>(a1s, a1d);                     // 6
    gat_aggregate_kernel<1><<<aggBlocks, 256>>>(b1);               // 7

    gemm_tc<2><<<ggrid, 256, SMEM_GEMM>>>(NN);                     // 8
    sdots_kernel<<<nwBlocks, 256>>>(a2s, a2d);                     // 9
    gat_aggregate_kernel<2><<<aggBlocks, 256>>>(b2);               // 10

    scan_seq_kernel<<<1, 256>>>(head, rel, g2l, simnb, simw);      // 11
    decode_kernel<<<(BB * 32 + 255) / 256, 256>>>(head, rel, tail, rel_emb, out);  // 12
}

// round 10
// speedup vs baseline: 1.6394x; 1.6394x over previous
#include <cuda_runtime.h>
#include <cuda_bf16.h>
#include <mma.h>
#include <math.h>
#include <stdint.h>

using namespace nvcuda;

// ---------------- problem constants ----------------
constexpr int NN  = 50000;
constexpr int EE  = 800000;
constexpr int HD  = 256;
constexpr int BB  = 256;
constexpr int ND  = 5000;
constexpr int KK  = 16;
constexpr int ER  = 20000;

// ---------------- device scratch (no allocs; zero-init at load, restored each call) ----
__device__ __align__(16) float g_h[(size_t)NN * HD];
__device__ __align__(16) float g_emb[(size_t)NN * HD];
__device__ __align__(16) __nv_bfloat16 g_xhi[(size_t)NN * HD];
__device__ __align__(16) __nv_bfloat16 g_xlo[(size_t)NN * HD];
__device__ __align__(16) __nv_bfloat16 g_acthi[(size_t)NN * HD];
__device__ __align__(16) __nv_bfloat16 g_actlo[(size_t)NN * HD];
__device__ __align__(16) __nv_bfloat16 g_w1hi[256 * 256];
__device__ __align__(16) __nv_bfloat16 g_w1lo[256 * 256];
__device__ __align__(16) __nv_bfloat16 g_w2hi[256 * 256];
__device__ __align__(16) __nv_bfloat16 g_w2lo[256 * 256];
__device__ float g_ssrc[NN];     // zero at gemm entry (restored by zero_mid / tail)
__device__ float g_sdst[NN];
__device__ int   g_deg[NN];      // zero at hist entry (restored by zero_mid)
__device__ int   g_cursor[NN];
__device__ int   g_rowptr[NN + 1];
__device__ int   g_csr_src[EE];
__device__ int   g_cnt[3 * ND];  // zero at hist entry (restored by tail)

constexpr int PB = 128;
constexpr int CHUNK = (NN + PB - 1) / PB;  // 391
__device__ int g_part[PB];

// ---------------- helpers ----------------
__device__ __forceinline__ uint32_t smem_u32(const void* p) {
    uint32_t a;
    asm("{ .reg .u64 t; cvta.to.shared.u64 t, %1; cvt.u32.u64 %0, t; }" : "=r"(a) : "l"(p));
    return a;
}
__device__ __forceinline__ void cp16(uint32_t dst, const void* src) {
    asm volatile("cp.async.cg.shared.global [%0], [%1], 16;" :: "r"(dst), "l"(src));
}

// ---------------- prep: x split + W1/W2 splits ----------------
__global__ void prep_all_kernel(const float* __restrict__ x,
                                const float* __restrict__ W1,
                                const float* __restrict__ W2) {
    int i = blockIdx.x * blockDim.x + threadIdx.x;
    if (i < NN * HD) {
        float v = x[i];
        __nv_bfloat16 h = __float2bfloat16(v);
        g_xhi[i] = h;
        g_xlo[i] = __float2bfloat16(v - __bfloat162float(h));
    }
    if (i < 256 * 256) {
        float v1 = W1[i];
        __nv_bfloat16 h1 = __float2bfloat16(v1);
        g_w1hi[i] = h1;
        g_w1lo[i] = __float2bfloat16(v1 - __bfloat162float(h1));
        float v2 = W2[i];
        __nv_bfloat16 h2 = __float2bfloat16(v2);
        g_w2hi[i] = h2;
        g_w2lo[i] = __float2bfloat16(v2 - __bfloat162float(h2));
    }
    if (i == 0) g_rowptr[NN] = EE;
}

// ---------------- fused histograms (deg/cnt are zero on entry) ----------------
__global__ void hist_kernel(const int* __restrict__ dst, const int* __restrict__ res) {
    int e = blockIdx.x * blockDim.x + threadIdx.x;
    if (e < EE) atomicAdd(&g_deg[dst[e]], 1);
    if (e < 3 * ER) atomicAdd(&g_cnt[(e / ER) * ND + res[e]], 1);
}

__global__ void partial_kernel() {
    __shared__ int sh[256];
    int b = blockIdx.x, t = threadIdx.x;
    int base = b * CHUNK;
    int s = 0;
    for (int i = t; i < CHUNK; i += 256) {
        int idx = base + i;
        if (idx < NN) s += g_deg[idx];
    }
    sh[t] = s;
    __syncthreads();
    for (int off = 128; off; off >>= 1) {
        if (t < off) sh[t] += sh[t + off];
        __syncthreads();
    }
    if (t == 0) g_part[b] = sh[0];
}

__global__ void rowptr_kernel() {
    __shared__ int red[128];
    __shared__ int s[512];
    int b = blockIdx.x, t = threadIdx.x;
    if (t < 128) red[t] = (t < b) ? g_part[t] : 0;
    __syncthreads();
    for (int off = 64; off; off >>= 1) {
        if (t < off) red[t] += red[t + off];
        __syncthreads();
    }
    int base = red[0];
    int idx = b * CHUNK + t;
    int v = (t < CHUNK && idx < NN) ? g_deg[idx] : 0;
    s[t] = v;
    __syncthreads();
    for (int off = 1; off < 512; off <<= 1) {
        int u = (t >= off) ? s[t - off] : 0;
        __syncthreads();
        s[t] += u;
        __syncthreads();
    }
    if (t < CHUNK && idx < NN) g_rowptr[idx] = base + s[t] - v;
}

__global__ void scatter_kernel(const int* __restrict__ src, const int* __restrict__ dst) {
    int e = blockIdx.x * blockDim.x + threadIdx.x;
    if (e < EE) {
        int d = dst[e];
        int pos = atomicAdd(&g_cursor[d], 1);
        g_csr_src[g_rowptr[d] + pos] = src[e];
    }
}

// ---------------- mid/tail state-restore zeroing ----------------
__global__ void zero_mid_kernel() {   // after agg<1>, before gemm<2>
    int i = blockIdx.x * blockDim.x + threadIdx.x;
    if (i < NN) { g_deg[i] = 0; g_cursor[i] = 0; g_ssrc[i] = 0.f; g_sdst[i] = 0.f; }
}
__global__ void tail_zero_kernel() {  // end of replay
    int i = blockIdx.x * blockDim.x + threadIdx.x;
    if (i < NN) { g_ssrc[i] = 0.f; g_sdst[i] = 0.f; }
    if (i < 3 * ND) g_cnt[i] = 0;
}

// ---------------- WMMA bf16 GEMM, 3xBF16, cp.async 2-buffer, fused attention dots ----
constexpr int BM = 128, BN = 128, KC = 32;
constexpr int LDA = KC + 8;
constexpr int LDB = BN + 8;
constexpr int SZ_A = BM * LDA * 2;
constexpr int SZ_B = KC * LDB * 2;
constexpr int OFF_AH = 0;
constexpr int OFF_AL = SZ_A;
constexpr int OFF_BH = 2 * SZ_A;
constexpr int OFF_BL = 2 * SZ_A + SZ_B;
constexpr int BUF = 2 * SZ_A + 2 * SZ_B;   // 37888
constexpr int SMEM_GEMM = 2 * BUF;         // 75776 (also holds 128x132 fp32 epi tile = 67584)

template <int LAYER>
__global__ __launch_bounds__(256, 2) void gemm_tc(const float* __restrict__ asrc,
                                                  const float* __restrict__ adst, int M) {
    const __nv_bfloat16* __restrict__ Ahi = (LAYER == 1) ? g_xhi : g_acthi;
    const __nv_bfloat16* __restrict__ Alo = (LAYER == 1) ? g_xlo : g_actlo;
    const __nv_bfloat16* __restrict__ Whi = (LAYER == 1) ? g_w1hi : g_w2hi;
    const __nv_bfloat16* __restrict__ Wlo = (LAYER == 1) ? g_w1lo : g_w2lo;

    extern __shared__ char smem[];
    uint32_t sb = smem_u32(smem);

    int tid = threadIdx.x;
    int wid = tid >> 5;
    int lane = tid & 31;
    int wm = wid & 3;
    int wn = wid >> 2;
    int row0 = blockIdx.x * BM;
    int col0 = blockIdx.y * BN;

    wmma::fragment<wmma::accumulator, 16, 16, 16, float> acc[2][4];
#pragma unroll
    for (int mt = 0; mt < 2; mt++)
#pragma unroll
        for (int nt = 0; nt < 4; nt++) wmma::fill_fragment(acc[mt][nt], 0.0f);

    auto load_chunk = [&](int c) {
        int kc = c * KC;
        uint32_t bb = sb + (c & 1) * BUF;
#pragma unroll
        for (int p = 0; p < 2; p++) {
            int t = p * 256 + tid;
            int r = t >> 2, seg = t & 3;
            int gr = row0 + r; if (gr >= M) gr = M - 1;
            size_t go = (size_t)gr * 256 + kc + seg * 8;
            uint32_t so = r * (LDA * 2) + seg * 16;
            cp16(bb + OFF_AH + so, Ahi + go);
            cp16(bb + OFF_AL + so, Alo + go);
        }
#pragma unroll
        for (int p = 0; p < 2; p++) {
            int t = p * 256 + tid;
            int k = t >> 4, seg = t & 15;
            size_t go = (size_t)(kc + k) * 256 + col0 + seg * 8;
            uint32_t so = k * (LDB * 2) + seg * 16;
            cp16(bb + OFF_BH + so, Whi + go);
            cp16(bb + OFF_BL + so, Wlo + go);
        }
        asm volatile("cp.async.commit_group;" ::: "memory");
    };

    load_chunk(0);

    for (int c = 0; c < 8; c++) {
        if (c < 7) {
            load_chunk(c + 1);
            asm volatile("cp.async.wait_group 1;" ::: "memory");
        } else {
            asm volatile("cp.async.wait_group 0;" ::: "memory");
        }
        __syncthreads();

        const char* buf = smem + (c & 1) * BUF;
        const __nv_bfloat16* bAh = (const __nv_bfloat16*)(buf + OFF_AH);
        const __nv_bfloat16* bAl = (const __nv_bfloat16*)(buf + OFF_AL);
        const __nv_bfloat16* bBh = (const __nv_bfloat16*)(buf + OFF_BH);
        const __nv_bfloat16* bBl = (const __nv_bfloat16*)(buf + OFF_BL);

#pragma unroll
        for (int s = 0; s < KC / 16; s++) {
            wmma::fragment<wmma::matrix_a, 16, 16, 16, __nv_bfloat16, wmma::row_major> ah[2], al[2];
#pragma unroll
            for (int mt = 0; mt < 2; mt++) {
                wmma::load_matrix_sync(ah[mt], bAh + (wm * 32 + mt * 16) * LDA + s * 16, LDA);
                wmma::load_matrix_sync(al[mt], bAl + (wm * 32 + mt * 16) * LDA + s * 16, LDA);
            }
#pragma unroll
            for (int nt = 0; nt < 4; nt++) {
                wmma::fragment<wmma::matrix_b, 16, 16, 16, __nv_bfloat16, wmma::row_major> bh, bl;
                wmma::load_matrix_sync(bh, bBh + (s * 16) * LDB + wn * 64 + nt * 16, LDB);
                wmma::load_matrix_sync(bl, bBl + (s * 16) * LDB + wn * 64 + nt * 16, LDB);
#pragma unroll
                for (int mt = 0; mt < 2; mt++) {
                    wmma::mma_sync(acc[mt][nt], ah[mt], bh, acc[mt][nt]);
                    wmma::mma_sync(acc[mt][nt], ah[mt], bl, acc[mt][nt]);
                    wmma::mma_sync(acc[mt][nt], al[mt], bh, acc[mt][nt]);
                }
            }
        }
        __syncthreads();
    }

    // ---- epilogue: stage C tile in smem, write g_h, fused partial dots ----
    float* smem_f = (float*)smem;  // 128 x 132 fp32 = 67584 B
#pragma unroll
    for (int mt = 0; mt < 2; mt++)
#pragma unroll
        for (int nt = 0; nt < 4; nt++)
            wmma::store_matrix_sync(smem_f + (wm * 32 + mt * 16) * 132 + wn * 64 + nt * 16,
                                    acc[mt][nt], 132, wmma::mem_row_major);
    __syncthreads();

    float4 af = *(const float4*)(asrc + col0 + lane * 4);
    float4 df = *(const float4*)(adst + col0 + lane * 4);
#pragma unroll 4
    for (int rr = 0; rr < 16; rr++) {
        int r = wid * 16 + rr;
        int grow = row0 + r;
        if (grow < M) {
            float4 v = *(float4*)(smem_f + r * 132 + lane * 4);
            *(float4*)(g_h + (size_t)grow * 256 + col0 + lane * 4) = v;
            float s1 = v.x * af.x + v.y * af.y + v.z * af.z + v.w * af.w;
            float s2 = v.x * df.x + v.y * df.y + v.z * df.z + v.w * df.w;
#pragma unroll
            for (int o = 16; o; o >>= 1) {
                s1 += __shfl_xor_sync(0xffffffffu, s1, o);
                s2 += __shfl_xor_sync(0xffffffffu, s2, o);
            }
            if (lane == 0) {
                atomicAdd(&g_ssrc[grow], s1);   // exactly 2 contributions -> deterministic
                atomicAdd(&g_sdst[grow], s2);
            }
        }
    }
}

// ---------------- fused GAT softmax + aggregation, warp per dst (R8 version) ----------
__device__ __forceinline__ float leaky02(float s) { return s > 0.f ? s : 0.2f * s; }

template <int LAYER>
__global__ __launch_bounds__(256) void gat_aggregate_kernel(const float* __restrict__ bias) {
    int w = (blockIdx.x * blockDim.x + threadIdx.x) >> 5;
    int lane = threadIdx.x & 31;
    if (w >= NN) return;

    int base = g_rowptr[w];
    int d = g_rowptr[w + 1] - base;
    float4 acc0 = make_float4(0.f, 0.f, 0.f, 0.f);
    float4 acc1 = make_float4(0.f, 0.f, 0.f, 0.f);

    if (d > 0) {
        float sdv = g_sdst[w];
        float e = -1e30f;
        if (lane < d) e = leaky02(g_ssrc[g_csr_src[base + lane]] + sdv);
        float mx = e;
        for (int i = 32 + lane; i < d; i += 32)
            mx = fmaxf(mx, leaky02(g_ssrc[g_csr_src[base + i]] + sdv));
#pragma unroll
        for (int o = 16; o; o >>= 1) mx = fmaxf(mx, __shfl_xor_sync(0xffffffffu, mx, o));
        float p = (lane < d) ? __expf(e - mx) : 0.f;
        float z = p;
        for (int i = 32 + lane; i < d; i += 32)
            z += __expf(leaky02(g_ssrc[g_csr_src[base + i]] + sdv) - mx);
#pragma unroll
        for (int o = 16; o; o >>= 1) z += __shfl_xor_sync(0xffffffffu, z, o);
        float invz = 1.f / (z + 1e-16f);
        float pn = p * invz;

        int dcap = d < 32 ? d : 32;
#pragma unroll 4
        for (int i = 0; i < dcap; i++) {
            float a = __shfl_sync(0xffffffffu, pn, i);
            int src = g_csr_src[base + i];
            const float4* hp = (const float4*)(g_h + (size_t)src * 256);
            float4 v0 = hp[lane];
            float4 v1 = hp[32 + lane];
            acc0.x += a * v0.x; acc0.y += a * v0.y; acc0.z += a * v0.z; acc0.w += a * v0.w;
            acc1.x += a * v1.x; acc1.y += a * v1.y; acc1.z += a * v1.z; acc1.w += a * v1.w;
        }
        for (int i = 32; i < d; i++) {
            int src = g_csr_src[base + i];
            float a = __expf(leaky02(g_ssrc[src] + sdv) - mx) * invz;
            const float4* hp = (const float4*)(g_h + (size_t)src * 256);
            float4 v0 = hp[lane];
            float4 v1 = hp[32 + lane];
            acc0.x += a * v0.x; acc0.y += a * v0.y; acc0.z += a * v0.z; acc0.w += a * v0.w;
            acc1.x += a * v1.x; acc1.y += a * v1.y; acc1.z += a * v1.z; acc1.w += a * v1.w;
        }
    }

    const float4* b4 = (const float4*)bias;
    float4 bb0 = b4[lane], bb1 = b4[32 + lane];
    acc0.x += bb0.x; acc0.y += bb0.y; acc0.z += bb0.z; acc0.w += bb0.w;
    acc1.x += bb1.x; acc1.y += bb1.y; acc1.z += bb1.z; acc1.w += bb1.w;

    if (LAYER == 1) {
        float v[8] = {acc0.x, acc0.y, acc0.z, acc0.w, acc1.x, acc1.y, acc1.z, acc1.w};
#pragma unroll
        for (int j = 0; j < 8; j++) v[j] = v[j] / (1.f + __expf(-v[j]));
        size_t o0 = (size_t)w * 256 + lane * 4;
#pragma unroll
        for (int j = 0; j < 4; j++) {
            __nv_bfloat16 h = __float2bfloat16(v[j]);
            g_acthi[o0 + j] = h;
            g_actlo[o0 + j] = __float2bfloat16(v[j] - __bfloat162float(h));
        }
        size_t o1 = o0 + 128;
#pragma unroll
        for (int j = 0; j < 4; j++) {
            __nv_bfloat16 h = __float2bfloat16(v[4 + j]);
            g_acthi[o1 + j] = h;
            g_actlo[o1 + j] = __float2bfloat16(v[4 + j] - __bfloat162float(h));
        }
    } else {
        float4* o4 = (float4*)(g_emb + (size_t)w * 256);
        o4[lane] = acc0;
        o4[32 + lane] = acc1;
    }
}

// ---------------- sequential per-triplet scan, smem-prefetched indices ----------------
__global__ void scan_seq_kernel(const int* __restrict__ head, const int* __restrict__ rel,
                                const int* __restrict__ g2l, const int* __restrict__ nb,
                                const float* __restrict__ wts) {
    __shared__ int   s_hi[BB];
    __shared__ int   s_dis[BB];
    __shared__ float s_c[BB];
    __shared__ int   s_nb[BB * KK];
    __shared__ float s_wt[BB * KK];
    int tid = threadIdx.x;  // 256 threads; thread owns embedding column tid

    // parallel prologue: resolve the whole per-step index chain up front
    {
        int r = rel[tid];
        int hi = head[tid];
        int dis = (r >= 4) && (r <= 6);
        s_hi[tid] = hi;
        s_dis[tid] = dis;
        if (dis) {
            int local = g2l[hi];
            float deg = (float)g_cnt[(r - 4) * ND + local];
            s_c[tid] = 0.7f * __expf(-0.7f * deg) + 0.2f;
#pragma unroll
            for (int k = 0; k < KK; k++) {
                s_nb[tid * KK + k] = nb[local * KK + k];
                s_wt[tid * KK + k] = wts[local * KK + k];
            }
        }
    }
    __syncthreads();

    // serial (column-owned, no barriers needed)
    for (int t = 0; t < BB; t++) {
        if (!s_dis[t]) continue;
        int hi = s_hi[t];
        float c = s_c[t];
        float vec = 0.f;
#pragma unroll
        for (int k = 0; k < KK; k++)
            vec += s_wt[t * KK + k] * g_emb[(size_t)s_nb[t * KK + k] * 256 + tid];
        float cur = g_emb[(size_t)hi * 256 + tid];
        g_emb[(size_t)hi * 256 + tid] = c * vec + (1.f - c) * cur;
    }
}

// ---------------- DistMult decode + sigmoid ----------------
__global__ __launch_bounds__(256) void decode_kernel(const int* __restrict__ head,
                                                     const int* __restrict__ rel,
                                                     const int* __restrict__ tail,
                                                     const float* __restrict__ rel_emb,
                                                     float* __restrict__ out) {
    int w = (blockIdx.x * blockDim.x + threadIdx.x) >> 5;
    int lane = threadIdx.x & 31;
    if (w >= BB) return;
    int hi = head[w], ti = tail[w], r = rel[w];
    const float4* hp = (const float4*)(g_emb + (size_t)hi * 256);
    const float4* tp = (const float4*)(g_emb + (size_t)ti * 256);
    const float4* rp = (const float4*)(rel_emb + (size_t)r * 256);
    float4 h0 = hp[lane], h1 = hp[32 + lane];
    float4 t0 = tp[lane], t1 = tp[32 + lane];
    float4 r0 = rp[lane], r1 = rp[32 + lane];
    float s = h0.x * r0.x * t0.x + h0.y * r0.y * t0.y + h0.z * r0.z * t0.z + h0.w * r0.w * t0.w
            + h1.x * r1.x * t1.x + h1.y * r1.y * t1.y + h1.z * r1.z * t1.z + h1.w * r1.w * t1.w;
#pragma unroll
    for (int o = 16; o; o >>= 1) s += __shfl_xor_sync(0xffffffffu, s, o);
    if (lane == 0) out[w] = 1.f / (1.f + __expf(-s));
}

// ---------------- host launch ----------------
extern "C" void kernel_launch(void* const* d_in, const int* in_sizes, int n_in,
                              void* d_out, int out_size) {
    const float* x        = (const float*)d_in[0];
    const int*   eidx     = (const int*)d_in[1];
    const int*   head     = (const int*)d_in[2];
    const int*   rel      = (const int*)d_in[3];
    const int*   tail     = (const int*)d_in[4];
    const int*   g2l      = (const int*)d_in[5];
    const int*   reledge  = (const int*)d_in[6];
    const int*   simnb    = (const int*)d_in[7];
    const float* simw     = (const float*)d_in[8];
    const float* W1       = (const float*)d_in[9];
    const float* a1s      = (const float*)d_in[10];
    const float* a1d      = (const float*)d_in[11];
    const float* b1       = (const float*)d_in[12];
    const float* W2       = (const float*)d_in[13];
    const float* a2s      = (const float*)d_in[14];
    const float* a2d      = (const float*)d_in[15];
    const float* b2       = (const float*)d_in[16];
    const float* rel_emb  = (const float*)d_in[17];
    float* out = (float*)d_out;

    const int* src = eidx;
    const int* dst = eidx + EE;

    cudaFuncSetAttribute(gemm_tc<1>, cudaFuncAttributeMaxDynamicSharedMemorySize, SMEM_GEMM);
    cudaFuncSetAttribute(gemm_tc<2>, cudaFuncAttributeMaxDynamicSharedMemorySize, SMEM_GEMM);

    dim3 ggrid((NN + BM - 1) / BM, 2);
    int nwBlocks = (NN * 32 + 255) / 256;

    prep_all_kernel<<<(NN * HD + 255) / 256, 256>>>(x, W1, W2);         // 0
    hist_kernel<<<(EE + 255) / 256, 256>>>(dst, reledge);               // 1
    partial_kernel<<<PB, 256>>>();                                      // 2
    gemm_tc<1><<<ggrid, 256, SMEM_GEMM>>>(a1s, a1d, NN);                // 3 <- profiled
    rowptr_kernel<<<PB, 512>>>();                                       // 4
    scatter_kernel<<<(EE + 255) / 256, 256>>>(src, dst);                // 5
    gat_aggregate_kernel<1><<<nwBlocks, 256>>>(b1);                     // 6
    zero_mid_kernel<<<(NN + 255) / 256, 256>>>();                       // 7
    gemm_tc<2><<<ggrid, 256, SMEM_GEMM>>>(a2s, a2d, NN);                // 8
    gat_aggregate_kernel<2><<<nwBlocks, 256>>>(b2);                     // 9
    scan_seq_kernel<<<1, 256>>>(head, rel, g2l, simnb, simw);           // 10
    decode_kernel<<<(BB * 32 + 255) / 256, 256>>>(head, rel, tail, rel_emb, out);  // 11
    tail_zero_kernel<<<(NN + 255) / 256, 256>>>();                      // 12
}

// round 11
// speedup vs baseline: 1.7011x; 1.0376x over previous
#include <cuda_runtime.h>
#include <cuda_bf16.h>
#include <mma.h>
#include <math.h>
#include <stdint.h>

using namespace nvcuda;

// ---------------- problem constants ----------------
constexpr int NN  = 50000;
constexpr int EE  = 800000;
constexpr int HD  = 256;
constexpr int BB  = 256;
constexpr int ND  = 5000;
constexpr int KK  = 16;
constexpr int ER  = 20000;

// ---------------- device scratch (no allocs; zero-init at load, restored each call) ----
__device__ __align__(16) float g_h[(size_t)NN * HD];
__device__ __align__(16) float g_emb[(size_t)NN * HD];
__device__ __align__(16) __nv_bfloat16 g_xhi[(size_t)NN * HD];
__device__ __align__(16) __nv_bfloat16 g_xlo[(size_t)NN * HD];
__device__ __align__(16) __nv_bfloat16 g_acthi[(size_t)NN * HD];
__device__ __align__(16) __nv_bfloat16 g_actlo[(size_t)NN * HD];
__device__ __align__(16) __nv_bfloat16 g_w1hi[256 * 256];
__device__ __align__(16) __nv_bfloat16 g_w1lo[256 * 256];
__device__ __align__(16) __nv_bfloat16 g_w2hi[256 * 256];
__device__ __align__(16) __nv_bfloat16 g_w2lo[256 * 256];
__device__ float g_ssrc[NN];     // zeroed by zero_mid / tail_zero
__device__ float g_sdst[NN];
__device__ int   g_deg[NN];      // zeroed by zero_mid
__device__ int   g_cursor[NN];
__device__ int   g_rowptr[NN + 1];
__device__ int   g_csr_src[EE];
__device__ int   g_cnt[3 * ND];  // zeroed by tail_zero

constexpr int PB = 128;
constexpr int CHUNK = (NN + PB - 1) / PB;  // 391
__device__ int g_part[PB];

// ---------------- helpers ----------------
__device__ __forceinline__ uint32_t smem_u32(const void* p) {
    uint32_t a;
    asm("{ .reg .u64 t; cvta.to.shared.u64 t, %1; cvt.u32.u64 %0, t; }" : "=r"(a) : "l"(p));
    return a;
}
__device__ __forceinline__ void cp16(uint32_t dst, const void* src) {
    asm volatile("cp.async.cg.shared.global [%0], [%1], 16;" :: "r"(dst), "l"(src));
}

// ---------------- prep: x split + W1/W2 splits ----------------
__global__ void prep_all_kernel(const float* __restrict__ x,
                                const float* __restrict__ W1,
                                const float* __restrict__ W2) {
    int i = blockIdx.x * blockDim.x + threadIdx.x;
    if (i < NN * HD) {
        float v = x[i];
        __nv_bfloat16 h = __float2bfloat16(v);
        g_xhi[i] = h;
        g_xlo[i] = __float2bfloat16(v - __bfloat162float(h));
    }
    if (i < 256 * 256) {
        float v1 = W1[i];
        __nv_bfloat16 h1 = __float2bfloat16(v1);
        g_w1hi[i] = h1;
        g_w1lo[i] = __float2bfloat16(v1 - __bfloat162float(h1));
        float v2 = W2[i];
        __nv_bfloat16 h2 = __float2bfloat16(v2);
        g_w2hi[i] = h2;
        g_w2lo[i] = __float2bfloat16(v2 - __bfloat162float(h2));
    }
    if (i == 0) g_rowptr[NN] = EE;
}

// ---------------- fused histograms (deg/cnt are zero on entry) ----------------
__global__ void hist_kernel(const int* __restrict__ dst, const int* __restrict__ res) {
    int e = blockIdx.x * blockDim.x + threadIdx.x;
    if (e < EE) atomicAdd(&g_deg[dst[e]], 1);
    if (e < 3 * ER) atomicAdd(&g_cnt[(e / ER) * ND + res[e]], 1);
}

__global__ void partial_kernel() {
    __shared__ int sh[256];
    int b = blockIdx.x, t = threadIdx.x;
    int base = b * CHUNK;
    int s = 0;
    for (int i = t; i < CHUNK; i += 256) {
        int idx = base + i;
        if (idx < NN) s += g_deg[idx];
    }
    sh[t] = s;
    __syncthreads();
    for (int off = 128; off; off >>= 1) {
        if (t < off) sh[t] += sh[t + off];
        __syncthreads();
    }
    if (t == 0) g_part[b] = sh[0];
}

__global__ void rowptr_kernel() {
    __shared__ int red[128];
    __shared__ int s[512];
    int b = blockIdx.x, t = threadIdx.x;
    if (t < 128) red[t] = (t < b) ? g_part[t] : 0;
    __syncthreads();
    for (int off = 64; off; off >>= 1) {
        if (t < off) red[t] += red[t + off];
        __syncthreads();
    }
    int base = red[0];
    int idx = b * CHUNK + t;
    int v = (t < CHUNK && idx < NN) ? g_deg[idx] : 0;
    s[t] = v;
    __syncthreads();
    for (int off = 1; off < 512; off <<= 1) {
        int u = (t >= off) ? s[t - off] : 0;
        __syncthreads();
        s[t] += u;
        __syncthreads();
    }
    if (t < CHUNK && idx < NN) g_rowptr[idx] = base + s[t] - v;
}

__global__ void scatter_kernel(const int* __restrict__ src, const int* __restrict__ dst) {
    int e = blockIdx.x * blockDim.x + threadIdx.x;
    if (e < EE) {
        int d = dst[e];
        int pos = atomicAdd(&g_cursor[d], 1);
        g_csr_src[g_rowptr[d] + pos] = src[e];
    }
}

// ---------------- mid/tail state-restore zeroing ----------------
__global__ void zero_mid_kernel() {   // after agg<1>, before gemm<2>
    int i = blockIdx.x * blockDim.x + threadIdx.x;
    if (i < NN) { g_deg[i] = 0; g_cursor[i] = 0; g_ssrc[i] = 0.f; g_sdst[i] = 0.f; }
}
__global__ void tail_zero_kernel() {  // end of replay
    int i = blockIdx.x * blockDim.x + threadIdx.x;
    if (i < NN) { g_ssrc[i] = 0.f; g_sdst[i] = 0.f; }
    if (i < 3 * ND) g_cnt[i] = 0;
}

// ---------------- WMMA bf16 GEMM, 3xBF16, cp.async 2-buffer, fused attention dots ----
constexpr int BM = 128, BN = 128, KC = 32;
constexpr int LDA = KC + 8;
constexpr int LDB = BN + 8;
constexpr int SZ_A = BM * LDA * 2;
constexpr int SZ_B = KC * LDB * 2;
constexpr int OFF_AH = 0;
constexpr int OFF_AL = SZ_A;
constexpr int OFF_BH = 2 * SZ_A;
constexpr int OFF_BL = 2 * SZ_A + SZ_B;
constexpr int BUF = 2 * SZ_A + 2 * SZ_B;   // 37888
constexpr int SMEM_GEMM = 2 * BUF;         // 75776

template <int LAYER>
__global__ __launch_bounds__(256, 2) void gemm_tc(const float* __restrict__ asrc,
                                                  const float* __restrict__ adst, int M) {
    const __nv_bfloat16* __restrict__ Ahi = (LAYER == 1) ? g_xhi : g_acthi;
    const __nv_bfloat16* __restrict__ Alo = (LAYER == 1) ? g_xlo : g_actlo;
    const __nv_bfloat16* __restrict__ Whi = (LAYER == 1) ? g_w1hi : g_w2hi;
    const __nv_bfloat16* __restrict__ Wlo = (LAYER == 1) ? g_w1lo : g_w2lo;

    extern __shared__ char smem[];
    uint32_t sb = smem_u32(smem);

    int tid = threadIdx.x;
    int wid = tid >> 5;
    int lane = tid & 31;
    int wm = wid & 3;
    int wn = wid >> 2;
    int row0 = blockIdx.x * BM;
    int col0 = blockIdx.y * BN;

    wmma::fragment<wmma::accumulator, 16, 16, 16, float> acc[2][4];
#pragma unroll
    for (int mt = 0; mt < 2; mt++)
#pragma unroll
        for (int nt = 0; nt < 4; nt++) wmma::fill_fragment(acc[mt][nt], 0.0f);

    auto load_chunk = [&](int c) {
        int kc = c * KC;
        uint32_t bb = sb + (c & 1) * BUF;
#pragma unroll
        for (int p = 0; p < 2; p++) {
            int t = p * 256 + tid;
            int r = t >> 2, seg = t & 3;
            int gr = row0 + r; if (gr >= M) gr = M - 1;
            size_t go = (size_t)gr * 256 + kc + seg * 8;
            uint32_t so = r * (LDA * 2) + seg * 16;
            cp16(bb + OFF_AH + so, Ahi + go);
            cp16(bb + OFF_AL + so, Alo + go);
        }
#pragma unroll
        for (int p = 0; p < 2; p++) {
            int t = p * 256 + tid;
            int k = t >> 4, seg = t & 15;
            size_t go = (size_t)(kc + k) * 256 + col0 + seg * 8;
            uint32_t so = k * (LDB * 2) + seg * 16;
            cp16(bb + OFF_BH + so, Whi + go);
            cp16(bb + OFF_BL + so, Wlo + go);
        }
        asm volatile("cp.async.commit_group;" ::: "memory");
    };

    load_chunk(0);

    for (int c = 0; c < 8; c++) {
        if (c < 7) {
            load_chunk(c + 1);
            asm volatile("cp.async.wait_group 1;" ::: "memory");
        } else {
            asm volatile("cp.async.wait_group 0;" ::: "memory");
        }
        __syncthreads();

        const char* buf = smem + (c & 1) * BUF;
        const __nv_bfloat16* bAh = (const __nv_bfloat16*)(buf + OFF_AH);
        const __nv_bfloat16* bAl = (const __nv_bfloat16*)(buf + OFF_AL);
        const __nv_bfloat16* bBh = (const __nv_bfloat16*)(buf + OFF_BH);
        const __nv_bfloat16* bBl = (const __nv_bfloat16*)(buf + OFF_BL);

#pragma unroll
        for (int s = 0; s < KC / 16; s++) {
            wmma::fragment<wmma::matrix_a, 16, 16, 16, __nv_bfloat16, wmma::row_major> ah[2], al[2];
#pragma unroll
            for (int mt = 0; mt < 2; mt++) {
                wmma::load_matrix_sync(ah[mt], bAh + (wm * 32 + mt * 16) * LDA + s * 16, LDA);
                wmma::load_matrix_sync(al[mt], bAl + (wm * 32 + mt * 16) * LDA + s * 16, LDA);
            }
#pragma unroll
            for (int nt = 0; nt < 4; nt++) {
                wmma::fragment<wmma::matrix_b, 16, 16, 16, __nv_bfloat16, wmma::row_major> bh, bl;
                wmma::load_matrix_sync(bh, bBh + (s * 16) * LDB + wn * 64 + nt * 16, LDB);
                wmma::load_matrix_sync(bl, bBl + (s * 16) * LDB + wn * 64 + nt * 16, LDB);
#pragma unroll
                for (int mt = 0; mt < 2; mt++) {
                    wmma::mma_sync(acc[mt][nt], ah[mt], bh, acc[mt][nt]);
                    wmma::mma_sync(acc[mt][nt], ah[mt], bl, acc[mt][nt]);
                    wmma::mma_sync(acc[mt][nt], al[mt], bh, acc[mt][nt]);
                }
            }
        }
        __syncthreads();
    }

    // ---- epilogue: stage C tile in smem, write g_h, fused partial dots ----
    float* smem_f = (float*)smem;  // 128 x 132 fp32 = 67584 B
#pragma unroll
    for (int mt = 0; mt < 2; mt++)
#pragma unroll
        for (int nt = 0; nt < 4; nt++)
            wmma::store_matrix_sync(smem_f + (wm * 32 + mt * 16) * 132 + wn * 64 + nt * 16,
                                    acc[mt][nt], 132, wmma::mem_row_major);
    __syncthreads();

    float4 af = *(const float4*)(asrc + col0 + lane * 4);
    float4 df = *(const float4*)(adst + col0 + lane * 4);
#pragma unroll 4
    for (int rr = 0; rr < 16; rr++) {
        int r = wid * 16 + rr;
        int grow = row0 + r;
        if (grow < M) {
            float4 v = *(float4*)(smem_f + r * 132 + lane * 4);
            *(float4*)(g_h + (size_t)grow * 256 + col0 + lane * 4) = v;
            float s1 = v.x * af.x + v.y * af.y + v.z * af.z + v.w * af.w;
            float s2 = v.x * df.x + v.y * df.y + v.z * df.z + v.w * df.w;
#pragma unroll
            for (int o = 16; o; o >>= 1) {
                s1 += __shfl_xor_sync(0xffffffffu, s1, o);
                s2 += __shfl_xor_sync(0xffffffffu, s2, o);
            }
            if (lane == 0) {
                atomicAdd(&g_ssrc[grow], s1);
                atomicAdd(&g_sdst[grow], s2);
            }
        }
    }
}

// ---------------- fused GAT softmax + aggregation, warp per dst ----------
__device__ __forceinline__ float leaky02(float s) { return s > 0.f ? s : 0.2f * s; }

template <int LAYER>
__global__ __launch_bounds__(256) void gat_aggregate_kernel(const float* __restrict__ bias) {
    int w = (blockIdx.x * blockDim.x + threadIdx.x) >> 5;
    int lane = threadIdx.x & 31;
    if (w >= NN) return;

    int base = g_rowptr[w];
    int d = g_rowptr[w + 1] - base;
    float4 acc0 = make_float4(0.f, 0.f, 0.f, 0.f);
    float4 acc1 = make_float4(0.f, 0.f, 0.f, 0.f);

    if (d > 0) {
        float sdv = g_sdst[w];
        float e = -1e30f;
        if (lane < d) e = leaky02(g_ssrc[g_csr_src[base + lane]] + sdv);
        float mx = e;
        for (int i = 32 + lane; i < d; i += 32)
            mx = fmaxf(mx, leaky02(g_ssrc[g_csr_src[base + i]] + sdv));
#pragma unroll
        for (int o = 16; o; o >>= 1) mx = fmaxf(mx, __shfl_xor_sync(0xffffffffu, mx, o));
        float p = (lane < d) ? __expf(e - mx) : 0.f;
        float z = p;
        for (int i = 32 + lane; i < d; i += 32)
            z += __expf(leaky02(g_ssrc[g_csr_src[base + i]] + sdv) - mx);
#pragma unroll
        for (int o = 16; o; o >>= 1) z += __shfl_xor_sync(0xffffffffu, z, o);
        float invz = 1.f / (z + 1e-16f);
        float pn = p * invz;

        int dcap = d < 32 ? d : 32;
#pragma unroll 4
        for (int i = 0; i < dcap; i++) {
            float a = __shfl_sync(0xffffffffu, pn, i);
            int src = g_csr_src[base + i];
            const float4* hp = (const float4*)(g_h + (size_t)src * 256);
            float4 v0 = hp[lane];
            float4 v1 = hp[32 + lane];
            acc0.x += a * v0.x; acc0.y += a * v0.y; acc0.z += a * v0.z; acc0.w += a * v0.w;
            acc1.x += a * v1.x; acc1.y += a * v1.y; acc1.z += a * v1.z; acc1.w += a * v1.w;
        }
        for (int i = 32; i < d; i++) {
            int src = g_csr_src[base + i];
            float a = __expf(leaky02(g_ssrc[src] + sdv) - mx) * invz;
            const float4* hp = (const float4*)(g_h + (size_t)src * 256);
            float4 v0 = hp[lane];
            float4 v1 = hp[32 + lane];
            acc0.x += a * v0.x; acc0.y += a * v0.y; acc0.z += a * v0.z; acc0.w += a * v0.w;
            acc1.x += a * v1.x; acc1.y += a * v1.y; acc1.z += a * v1.z; acc1.w += a * v1.w;
        }
    }

    const float4* b4 = (const float4*)bias;
    float4 bb0 = b4[lane], bb1 = b4[32 + lane];
    acc0.x += bb0.x; acc0.y += bb0.y; acc0.z += bb0.z; acc0.w += bb0.w;
    acc1.x += bb1.x; acc1.y += bb1.y; acc1.z += bb1.z; acc1.w += bb1.w;

    if (LAYER == 1) {
        float v[8] = {acc0.x, acc0.y, acc0.z, acc0.w, acc1.x, acc1.y, acc1.z, acc1.w};
#pragma unroll
        for (int j = 0; j < 8; j++) v[j] = v[j] / (1.f + __expf(-v[j]));
        size_t o0 = (size_t)w * 256 + lane * 4;
#pragma unroll
        for (int j = 0; j < 4; j++) {
            __nv_bfloat16 h = __float2bfloat16(v[j]);
            g_acthi[o0 + j] = h;
            g_actlo[o0 + j] = __float2bfloat16(v[j] - __bfloat162float(h));
        }
        size_t o1 = o0 + 128;
#pragma unroll
        for (int j = 0; j < 4; j++) {
            __nv_bfloat16 h = __float2bfloat16(v[4 + j]);
            g_acthi[o1 + j] = h;
            g_actlo[o1 + j] = __float2bfloat16(v[4 + j] - __bfloat162float(h));
        }
    } else {
        float4* o4 = (float4*)(g_emb + (size_t)w * 256);
        o4[lane] = acc0;
        o4[32 + lane] = acc1;
    }
}

// ---------------- sequential per-triplet scan, smem-prefetched indices ----------------
__global__ void scan_seq_kernel(const int* __restrict__ head, const int* __restrict__ rel,
                                const int* __restrict__ g2l, const int* __restrict__ nb,
                                const float* __restrict__ wts) {
    __shared__ int   s_hi[BB];
    __shared__ int   s_dis[BB];
    __shared__ float s_c[BB];
    __shared__ int   s_nb[BB * KK];
    __shared__ float s_wt[BB * KK];
    int tid = threadIdx.x;

    {
        int r = rel[tid];
        int hi = head[tid];
        int dis = (r >= 4) && (r <= 6);
        s_hi[tid] = hi;
        s_dis[tid] = dis;
        if (dis) {
            int local = g2l[hi];
            float deg = (float)g_cnt[(r - 4) * ND + local];
            s_c[tid] = 0.7f * __expf(-0.7f * deg) + 0.2f;
#pragma unroll
            for (int k = 0; k < KK; k++) {
                s_nb[tid * KK + k] = nb[local * KK + k];
                s_wt[tid * KK + k] = wts[local * KK + k];
            }
        }
    }
    __syncthreads();

    for (int t = 0; t < BB; t++) {
        if (!s_dis[t]) continue;
        int hi = s_hi[t];
        float c = s_c[t];
        float vec = 0.f;
#pragma unroll
        for (int k = 0; k < KK; k++)
            vec += s_wt[t * KK + k] * g_emb[(size_t)s_nb[t * KK + k] * 256 + tid];
        float cur = g_emb[(size_t)hi * 256 + tid];
        g_emb[(size_t)hi * 256 + tid] = c * vec + (1.f - c) * cur;
    }
}

// ---------------- DistMult decode + sigmoid ----------------
__global__ __launch_bounds__(256) void decode_kernel(const int* __restrict__ head,
                                                     const int* __restrict__ rel,
                                                     const int* __restrict__ tail,
                                                     const float* __restrict__ rel_emb,
                                                     float* __restrict__ out) {
    int w = (blockIdx.x * blockDim.x + threadIdx.x) >> 5;
    int lane = threadIdx.x & 31;
    if (w >= BB) return;
    int hi = head[w], ti = tail[w], r = rel[w];
    const float4* hp = (const float4*)(g_emb + (size_t)hi * 256);
    const float4* tp = (const float4*)(g_emb + (size_t)ti * 256);
    const float4* rp = (const float4*)(rel_emb + (size_t)r * 256);
    float4 h0 = hp[lane], h1 = hp[32 + lane];
    float4 t0 = tp[lane], t1 = tp[32 + lane];
    float4 r0 = rp[lane], r1 = rp[32 + lane];
    float s = h0.x * r0.x * t0.x + h0.y * r0.y * t0.y + h0.z * r0.z * t0.z + h0.w * r0.w * t0.w
            + h1.x * r1.x * t1.x + h1.y * r1.y * t1.y + h1.z * r1.z * t1.z + h1.w * r1.w * t1.w;
#pragma unroll
    for (int o = 16; o; o >>= 1) s += __shfl_xor_sync(0xffffffffu, s, o);
    if (lane == 0) out[w] = 1.f / (1.f + __expf(-s));
}

// ---------------- host launch ----------------
extern "C" void kernel_launch(void* const* d_in, const int* in_sizes, int n_in,
                              void* d_out, int out_size) {
    const float* x        = (const float*)d_in[0];
    const int*   eidx     = (const int*)d_in[1];
    const int*   head     = (const int*)d_in[2];
    const int*   rel      = (const int*)d_in[3];
    const int*   tail     = (const int*)d_in[4];
    const int*   g2l      = (const int*)d_in[5];
    const int*   reledge  = (const int*)d_in[6];
    const int*   simnb    = (const int*)d_in[7];
    const float* simw     = (const float*)d_in[8];
    const float* W1       = (const float*)d_in[9];
    const float* a1s      = (const float*)d_in[10];
    const float* a1d      = (const float*)d_in[11];
    const float* b1       = (const float*)d_in[12];
    const float* W2       = (const float*)d_in[13];
    const float* a2s      = (const float*)d_in[14];
    const float* a2d      = (const float*)d_in[15];
    const float* b2       = (const float*)d_in[16];
    const float* rel_emb  = (const float*)d_in[17];
    float* out = (float*)d_out;

    const int* src = eidx;
    const int* dst = eidx + EE;

    // one-time resources (host-side only; no device allocations)
    static cudaStream_t s2 = nullptr;
    static cudaEvent_t evFork = nullptr, evJoin = nullptr, evScan = nullptr, evTail = nullptr;
    if (s2 == nullptr) {
        cudaStreamCreateWithFlags(&s2, cudaStreamNonBlocking);
        cudaEventCreateWithFlags(&evFork, cudaEventDisableTiming);
        cudaEventCreateWithFlags(&evJoin, cudaEventDisableTiming);
        cudaEventCreateWithFlags(&evScan, cudaEventDisableTiming);
        cudaEventCreateWithFlags(&evTail, cudaEventDisableTiming);
    }

    cudaFuncSetAttribute(gemm_tc<1>, cudaFuncAttributeMaxDynamicSharedMemorySize, SMEM_GEMM);
    cudaFuncSetAttribute(gemm_tc<2>, cudaFuncAttributeMaxDynamicSharedMemorySize, SMEM_GEMM);

    dim3 ggrid((NN + BM - 1) / BM, 2);
    int nwBlocks = (NN * 32 + 255) / 256;

    // ---- fork: CSR build chain on s2, prep+gemm1 on main ----
    cudaEventRecord(evFork, 0);
    cudaStreamWaitEvent(s2, evFork, 0);

    hist_kernel<<<(EE + 255) / 256, 256, 0, s2>>>(dst, reledge);
    partial_kernel<<<PB, 256, 0, s2>>>();
    rowptr_kernel<<<PB, 512, 0, s2>>>();
    scatter_kernel<<<(EE + 255) / 256, 256, 0, s2>>>(src, dst);
    cudaEventRecord(evJoin, s2);

    prep_all_kernel<<<(NN * HD + 255) / 256, 256>>>(x, W1, W2);
    gemm_tc<1><<<ggrid, 256, SMEM_GEMM>>>(a1s, a1d, NN);

    // ---- join: aggregate needs CSR + gemm1 ----
    cudaStreamWaitEvent(0, evJoin, 0);
    gat_aggregate_kernel<1><<<nwBlocks, 256>>>(b1);
    zero_mid_kernel<<<(NN + 255) / 256, 256>>>();
    gemm_tc<2><<<ggrid, 256, SMEM_GEMM>>>(a2s, a2d, NN);
    gat_aggregate_kernel<2><<<nwBlocks, 256>>>(b2);
    scan_seq_kernel<<<1, 256>>>(head, rel, g2l, simnb, simw);

    // ---- tail_zero overlaps decode ----
    cudaEventRecord(evScan, 0);
    cudaStreamWaitEvent(s2, evScan, 0);
    tail_zero_kernel<<<(NN + 255) / 256, 256, 0, s2>>>();
    cudaEventRecord(evTail, s2);

    decode_kernel<<<(BB * 32 + 255) / 256, 256>>>(head, rel, tail, rel_emb, out);
    cudaStreamWaitEvent(0, evTail, 0);
}

// round 12
// speedup vs baseline: 1.7560x; 1.0323x over previous
#include <cuda_runtime.h>
#include <cuda_bf16.h>
#include <mma.h>
#include <math.h>
#include <stdint.h>

using namespace nvcuda;

// ---------------- problem constants ----------------
constexpr int NN  = 50000;
constexpr int EE  = 800000;
constexpr int HD  = 256;
constexpr int BB  = 256;
constexpr int ND  = 5000;
constexpr int KK  = 16;
constexpr int ER  = 20000;

// ---------------- device scratch (zero-init at load; tail_zero restores each replay) ----
__device__ __align__(16) float g_h[(size_t)NN * HD];
__device__ __align__(16) float g_emb[(size_t)NN * HD];
__device__ __align__(16) __nv_bfloat16 g_xhi[(size_t)NN * HD];
__device__ __align__(16) __nv_bfloat16 g_xlo[(size_t)NN * HD];
__device__ __align__(16) __nv_bfloat16 g_acthi[(size_t)NN * HD];
__device__ __align__(16) __nv_bfloat16 g_actlo[(size_t)NN * HD];
__device__ __align__(16) __nv_bfloat16 g_w1hi[256 * 256];
__device__ __align__(16) __nv_bfloat16 g_w1lo[256 * 256];
__device__ __align__(16) __nv_bfloat16 g_w2hi[256 * 256];
__device__ __align__(16) __nv_bfloat16 g_w2lo[256 * 256];
__device__ float g_ssrcA[NN];    // layer-1 dots (restored by tail_zero)
__device__ float g_sdstA[NN];
__device__ float g_ssrcB[NN];    // layer-2 dots
__device__ float g_sdstB[NN];
__device__ int   g_deg[NN];      // restored by tail_zero
__device__ int   g_cursor[NN];
__device__ int   g_rowptr[NN + 1];
__device__ int   g_csr_src[EE];
__device__ int   g_cnt[3 * ND];

constexpr int PB = 128;
constexpr int CHUNK = (NN + PB - 1) / PB;  // 391
__device__ int g_part[PB];

// ---------------- helpers ----------------
__device__ __forceinline__ uint32_t smem_u32(const void* p) {
    uint32_t a;
    asm("{ .reg .u64 t; cvta.to.shared.u64 t, %1; cvt.u32.u64 %0, t; }" : "=r"(a) : "l"(p));
    return a;
}
__device__ __forceinline__ void cp16(uint32_t dst, const void* src) {
    asm volatile("cp.async.cg.shared.global [%0], [%1], 16;" :: "r"(dst), "l"(src));
}

// ---------------- prep: x split + W1/W2 splits ----------------
__global__ void prep_all_kernel(const float* __restrict__ x,
                                const float* __restrict__ W1,
                                const float* __restrict__ W2) {
    int i = blockIdx.x * blockDim.x + threadIdx.x;
    if (i < NN * HD) {
        float v = x[i];
        __nv_bfloat16 h = __float2bfloat16(v);
        g_xhi[i] = h;
        g_xlo[i] = __float2bfloat16(v - __bfloat162float(h));
    }
    if (i < 256 * 256) {
        float v1 = W1[i];
        __nv_bfloat16 h1 = __float2bfloat16(v1);
        g_w1hi[i] = h1;
        g_w1lo[i] = __float2bfloat16(v1 - __bfloat162float(h1));
        float v2 = W2[i];
        __nv_bfloat16 h2 = __float2bfloat16(v2);
        g_w2hi[i] = h2;
        g_w2lo[i] = __float2bfloat16(v2 - __bfloat162float(h2));
    }
    if (i == 0) g_rowptr[NN] = EE;
}

// ---------------- fused histograms (deg/cnt are zero on entry) ----------------
__global__ void hist_kernel(const int* __restrict__ dst, const int* __restrict__ res) {
    int e = blockIdx.x * blockDim.x + threadIdx.x;
    if (e < EE) atomicAdd(&g_deg[dst[e]], 1);
    if (e < 3 * ER) atomicAdd(&g_cnt[(e / ER) * ND + res[e]], 1);
}

__global__ void partial_kernel() {
    __shared__ int sh[256];
    int b = blockIdx.x, t = threadIdx.x;
    int base = b * CHUNK;
    int s = 0;
    for (int i = t; i < CHUNK; i += 256) {
        int idx = base + i;
        if (idx < NN) s += g_deg[idx];
    }
    sh[t] = s;
    __syncthreads();
    for (int off = 128; off; off >>= 1) {
        if (t < off) sh[t] += sh[t + off];
        __syncthreads();
    }
    if (t == 0) g_part[b] = sh[0];
}

__global__ void rowptr_kernel() {
    __shared__ int red[128];
    __shared__ int s[512];
    int b = blockIdx.x, t = threadIdx.x;
    if (t < 128) red[t] = (t < b) ? g_part[t] : 0;
    __syncthreads();
    for (int off = 64; off; off >>= 1) {
        if (t < off) red[t] += red[t + off];
        __syncthreads();
    }
    int base = red[0];
    int idx = b * CHUNK + t;
    int v = (t < CHUNK && idx < NN) ? g_deg[idx] : 0;
    s[t] = v;
    __syncthreads();
    for (int off = 1; off < 512; off <<= 1) {
        int u = (t >= off) ? s[t - off] : 0;
        __syncthreads();
        s[t] += u;
        __syncthreads();
    }
    if (t < CHUNK && idx < NN) g_rowptr[idx] = base + s[t] - v;
}

__global__ void scatter_kernel(const int* __restrict__ src, const int* __restrict__ dst) {
    int e = blockIdx.x * blockDim.x + threadIdx.x;
    if (e < EE) {
        int d = dst[e];
        int pos = atomicAdd(&g_cursor[d], 1);
        g_csr_src[g_rowptr[d] + pos] = src[e];
    }
}

// ---------------- tail state-restore (runs on s2, overlapped with decode) ----------
__global__ void tail_zero_kernel() {
    int i = blockIdx.x * blockDim.x + threadIdx.x;
    if (i < NN) {
        g_ssrcA[i] = 0.f; g_sdstA[i] = 0.f;
        g_ssrcB[i] = 0.f; g_sdstB[i] = 0.f;
        g_deg[i] = 0; g_cursor[i] = 0;
    }
    if (i < 3 * ND) g_cnt[i] = 0;
}

// ---------------- WMMA bf16 GEMM, 3xBF16, cp.async 2-buffer, fused attention dots ----
constexpr int BM = 128, BN = 128, KC = 32;
constexpr int LDA = KC + 8;
constexpr int LDB = BN + 8;
constexpr int SZ_A = BM * LDA * 2;
constexpr int SZ_B = KC * LDB * 2;
constexpr int OFF_AH = 0;
constexpr int OFF_AL = SZ_A;
constexpr int OFF_BH = 2 * SZ_A;
constexpr int OFF_BL = 2 * SZ_A + SZ_B;
constexpr int BUF = 2 * SZ_A + 2 * SZ_B;   // 37888
constexpr int SMEM_GEMM = 2 * BUF;         // 75776

template <int LAYER>
__global__ __launch_bounds__(256, 2) void gemm_tc(const float* __restrict__ asrc,
                                                  const float* __restrict__ adst, int M) {
    const __nv_bfloat16* __restrict__ Ahi = (LAYER == 1) ? g_xhi : g_acthi;
    const __nv_bfloat16* __restrict__ Alo = (LAYER == 1) ? g_xlo : g_actlo;
    const __nv_bfloat16* __restrict__ Whi = (LAYER == 1) ? g_w1hi : g_w2hi;
    const __nv_bfloat16* __restrict__ Wlo = (LAYER == 1) ? g_w1lo : g_w2lo;
    float* __restrict__ ssrc = (LAYER == 1) ? g_ssrcA : g_ssrcB;
    float* __restrict__ sdst = (LAYER == 1) ? g_sdstA : g_sdstB;

    extern __shared__ char smem[];
    uint32_t sb = smem_u32(smem);

    int tid = threadIdx.x;
    int wid = tid >> 5;
    int lane = tid & 31;
    int wm = wid & 3;
    int wn = wid >> 2;
    int row0 = blockIdx.x * BM;
    int col0 = blockIdx.y * BN;

    wmma::fragment<wmma::accumulator, 16, 16, 16, float> acc[2][4];
#pragma unroll
    for (int mt = 0; mt < 2; mt++)
#pragma unroll
        for (int nt = 0; nt < 4; nt++) wmma::fill_fragment(acc[mt][nt], 0.0f);

    auto load_chunk = [&](int c) {
        int kc = c * KC;
        uint32_t bb = sb + (c & 1) * BUF;
#pragma unroll
        for (int p = 0; p < 2; p++) {
            int t = p * 256 + tid;
            int r = t >> 2, seg = t & 3;
            int gr = row0 + r; if (gr >= M) gr = M - 1;
            size_t go = (size_t)gr * 256 + kc + seg * 8;
            uint32_t so = r * (LDA * 2) + seg * 16;
            cp16(bb + OFF_AH + so, Ahi + go);
            cp16(bb + OFF_AL + so, Alo + go);
        }
#pragma unroll
        for (int p = 0; p < 2; p++) {
            int t = p * 256 + tid;
            int k = t >> 4, seg = t & 15;
            size_t go = (size_t)(kc + k) * 256 + col0 + seg * 8;
            uint32_t so = k * (LDB * 2) + seg * 16;
            cp16(bb + OFF_BH + so, Whi + go);
            cp16(bb + OFF_BL + so, Wlo + go);
        }
        asm volatile("cp.async.commit_group;" ::: "memory");
    };

    load_chunk(0);

    for (int c = 0; c < 8; c++) {
        if (c < 7) {
            load_chunk(c + 1);
            asm volatile("cp.async.wait_group 1;" ::: "memory");
        } else {
            asm volatile("cp.async.wait_group 0;" ::: "memory");
        }
        __syncthreads();

        const char* buf = smem + (c & 1) * BUF;
        const __nv_bfloat16* bAh = (const __nv_bfloat16*)(buf + OFF_AH);
        const __nv_bfloat16* bAl = (const __nv_bfloat16*)(buf + OFF_AL);
        const __nv_bfloat16* bBh = (const __nv_bfloat16*)(buf + OFF_BH);
        const __nv_bfloat16* bBl = (const __nv_bfloat16*)(buf + OFF_BL);

#pragma unroll
        for (int s = 0; s < KC / 16; s++) {
            wmma::fragment<wmma::matrix_a, 16, 16, 16, __nv_bfloat16, wmma::row_major> ah[2], al[2];
#pragma unroll
            for (int mt = 0; mt < 2; mt++) {
                wmma::load_matrix_sync(ah[mt], bAh + (wm * 32 + mt * 16) * LDA + s * 16, LDA);
                wmma::load_matrix_sync(al[mt], bAl + (wm * 32 + mt * 16) * LDA + s * 16, LDA);
            }
#pragma unroll
            for (int nt = 0; nt < 4; nt++) {
                wmma::fragment<wmma::matrix_b, 16, 16, 16, __nv_bfloat16, wmma::row_major> bh, bl;
                wmma::load_matrix_sync(bh, bBh + (s * 16) * LDB + wn * 64 + nt * 16, LDB);
                wmma::load_matrix_sync(bl, bBl + (s * 16) * LDB + wn * 64 + nt * 16, LDB);
#pragma unroll
                for (int mt = 0; mt < 2; mt++) {
                    wmma::mma_sync(acc[mt][nt], ah[mt], bh, acc[mt][nt]);
                    wmma::mma_sync(acc[mt][nt], ah[mt], bl, acc[mt][nt]);
                    wmma::mma_sync(acc[mt][nt], al[mt], bh, acc[mt][nt]);
                }
            }
        }
        __syncthreads();
    }

    // ---- epilogue: stage C tile in smem, write g_h, fused partial dots ----
    float* smem_f = (float*)smem;  // 128 x 132 fp32 = 67584 B
#pragma unroll
    for (int mt = 0; mt < 2; mt++)
#pragma unroll
        for (int nt = 0; nt < 4; nt++)
            wmma::store_matrix_sync(smem_f + (wm * 32 + mt * 16) * 132 + wn * 64 + nt * 16,
                                    acc[mt][nt], 132, wmma::mem_row_major);
    __syncthreads();

    float4 af = *(const float4*)(asrc + col0 + lane * 4);
    float4 df = *(const float4*)(adst + col0 + lane * 4);
#pragma unroll 4
    for (int rr = 0; rr < 16; rr++) {
        int r = wid * 16 + rr;
        int grow = row0 + r;
        if (grow < M) {
            float4 v = *(float4*)(smem_f + r * 132 + lane * 4);
            *(float4*)(g_h + (size_t)grow * 256 + col0 + lane * 4) = v;
            float s1 = v.x * af.x + v.y * af.y + v.z * af.z + v.w * af.w;
            float s2 = v.x * df.x + v.y * df.y + v.z * df.z + v.w * df.w;
#pragma unroll
            for (int o = 16; o; o >>= 1) {
                s1 += __shfl_xor_sync(0xffffffffu, s1, o);
                s2 += __shfl_xor_sync(0xffffffffu, s2, o);
            }
            if (lane == 0) {
                atomicAdd(&ssrc[grow], s1);   // exactly 2 contributions -> deterministic
                atomicAdd(&sdst[grow], s2);
            }
        }
    }
}

// ---------------- fused GAT softmax + aggregation, warp per dst ----------
__device__ __forceinline__ float leaky02(float s) { return s > 0.f ? s : 0.2f * s; }

template <int LAYER>
__global__ __launch_bounds__(256) void gat_aggregate_kernel(const float* __restrict__ bias) {
    const float* __restrict__ ssrc = (LAYER == 1) ? g_ssrcA : g_ssrcB;
    const float* __restrict__ sdst = (LAYER == 1) ? g_sdstA : g_sdstB;

    int w = (blockIdx.x * blockDim.x + threadIdx.x) >> 5;
    int lane = threadIdx.x & 31;
    if (w >= NN) return;

    int base = g_rowptr[w];
    int d = g_rowptr[w + 1] - base;
    float4 acc0 = make_float4(0.f, 0.f, 0.f, 0.f);
    float4 acc1 = make_float4(0.f, 0.f, 0.f, 0.f);

    if (d > 0) {
        float sdv = sdst[w];
        // cache first 32 edge indices + logits in registers (one per lane)
        int myidx = 0;
        float e = -1e30f;
        if (lane < d) {
            myidx = g_csr_src[base + lane];
            e = leaky02(ssrc[myidx] + sdv);
        }
        float mx = e;
        for (int i = 32 + lane; i < d; i += 32)
            mx = fmaxf(mx, leaky02(ssrc[g_csr_src[base + i]] + sdv));
#pragma unroll
        for (int o = 16; o; o >>= 1) mx = fmaxf(mx, __shfl_xor_sync(0xffffffffu, mx, o));
        float p = (lane < d) ? __expf(e - mx) : 0.f;
        float z = p;
        for (int i = 32 + lane; i < d; i += 32)
            z += __expf(leaky02(ssrc[g_csr_src[base + i]] + sdv) - mx);
#pragma unroll
        for (int o = 16; o; o >>= 1) z += __shfl_xor_sync(0xffffffffu, z, o);
        float invz = 1.f / (z + 1e-16f);
        float pn = p * invz;  // normalized weight for cached edge `lane`

        int dcap = d < 32 ? d : 32;
#pragma unroll 4
        for (int i = 0; i < dcap; i++) {
            float a = __shfl_sync(0xffffffffu, pn, i);
            int src = __shfl_sync(0xffffffffu, myidx, i);
            const float4* hp = (const float4*)(g_h + (size_t)src * 256);
            float4 v0 = hp[lane];
            float4 v1 = hp[32 + lane];
            acc0.x += a * v0.x; acc0.y += a * v0.y; acc0.z += a * v0.z; acc0.w += a * v0.w;
            acc1.x += a * v1.x; acc1.y += a * v1.y; acc1.z += a * v1.z; acc1.w += a * v1.w;
        }
        for (int i = 32; i < d; i++) {
            int src = g_csr_src[base + i];
            float a = __expf(leaky02(ssrc[src] + sdv) - mx) * invz;
            const float4* hp = (const float4*)(g_h + (size_t)src * 256);
            float4 v0 = hp[lane];
            float4 v1 = hp[32 + lane];
            acc0.x += a * v0.x; acc0.y += a * v0.y; acc0.z += a * v0.z; acc0.w += a * v0.w;
            acc1.x += a * v1.x; acc1.y += a * v1.y; acc1.z += a * v1.z; acc1.w += a * v1.w;
        }
    }

    const float4* b4 = (const float4*)bias;
    float4 bb0 = b4[lane], bb1 = b4[32 + lane];
    acc0.x += bb0.x; acc0.y += bb0.y; acc0.z += bb0.z; acc0.w += bb0.w;
    acc1.x += bb1.x; acc1.y += bb1.y; acc1.z += bb1.z; acc1.w += bb1.w;

    if (LAYER == 1) {
        float v[8] = {acc0.x, acc0.y, acc0.z, acc0.w, acc1.x, acc1.y, acc1.z, acc1.w};
#pragma unroll
        for (int j = 0; j < 8; j++) v[j] = v[j] / (1.f + __expf(-v[j]));
        size_t o0 = (size_t)w * 256 + lane * 4;
#pragma unroll
        for (int j = 0; j < 4; j++) {
            __nv_bfloat16 h = __float2bfloat16(v[j]);
            g_acthi[o0 + j] = h;
            g_actlo[o0 + j] = __float2bfloat16(v[j] - __bfloat162float(h));
        }
        size_t o1 = o0 + 128;
#pragma unroll
        for (int j = 0; j < 4; j++) {
            __nv_bfloat16 h = __float2bfloat16(v[4 + j]);
            g_acthi[o1 + j] = h;
            g_actlo[o1 + j] = __float2bfloat16(v[4 + j] - __bfloat162float(h));
        }
    } else {
        float4* o4 = (float4*)(g_emb + (size_t)w * 256);
        o4[lane] = acc0;
        o4[32 + lane] = acc1;
    }
}

// ---------------- sequential per-triplet scan, smem-prefetched indices ----------------
__global__ void scan_seq_kernel(const int* __restrict__ head, const int* __restrict__ rel,
                                const int* __restrict__ g2l, const int* __restrict__ nb,
                                const float* __restrict__ wts) {
    __shared__ int   s_hi[BB];
    __shared__ int   s_dis[BB];
    __shared__ float s_c[BB];
    __shared__ int   s_nb[BB * KK];
    __shared__ float s_wt[BB * KK];
    int tid = threadIdx.x;

    {
        int r = rel[tid];
        int hi = head[tid];
        int dis = (r >= 4) && (r <= 6);
        s_hi[tid] = hi;
        s_dis[tid] = dis;
        if (dis) {
            int local = g2l[hi];
            float deg = (float)g_cnt[(r - 4) * ND + local];
            s_c[tid] = 0.7f * __expf(-0.7f * deg) + 0.2f;
#pragma unroll
            for (int k = 0; k < KK; k++) {
                s_nb[tid * KK + k] = nb[local * KK + k];
                s_wt[tid * KK + k] = wts[local * KK + k];
            }
        }
    }
    __syncthreads();

    for (int t = 0; t < BB; t++) {
        if (!s_dis[t]) continue;
        int hi = s_hi[t];
        float c = s_c[t];
        float vec = 0.f;
#pragma unroll
        for (int k = 0; k < KK; k++)
            vec += s_wt[t * KK + k] * g_emb[(size_t)s_nb[t * KK + k] * 256 + tid];
        float cur = g_emb[(size_t)hi * 256 + tid];
        g_emb[(size_t)hi * 256 + tid] = c * vec + (1.f - c) * cur;
    }
}

// ---------------- DistMult decode + sigmoid ----------------
__global__ __launch_bounds__(256) void decode_kernel(const int* __restrict__ head,
                                                     const int* __restrict__ rel,
                                                     const int* __restrict__ tail,
                                                     const float* __restrict__ rel_emb,
                                                     float* __restrict__ out) {
    int w = (blockIdx.x * blockDim.x + threadIdx.x) >> 5;
    int lane = threadIdx.x & 31;
    if (w >= BB) return;
    int hi = head[w], ti = tail[w], r = rel[w];
    const float4* hp = (const float4*)(g_emb + (size_t)hi * 256);
    const float4* tp = (const float4*)(g_emb + (size_t)ti * 256);
    const float4* rp = (const float4*)(rel_emb + (size_t)r * 256);
    float4 h0 = hp[lane], h1 = hp[32 + lane];
    float4 t0 = tp[lane], t1 = tp[32 + lane];
    float4 r0 = rp[lane], r1 = rp[32 + lane];
    float s = h0.x * r0.x * t0.x + h0.y * r0.y * t0.y + h0.z * r0.z * t0.z + h0.w * r0.w * t0.w
            + h1.x * r1.x * t1.x + h1.y * r1.y * t1.y + h1.z * r1.z * t1.z + h1.w * r1.w * t1.w;
#pragma unroll
    for (int o = 16; o; o >>= 1) s += __shfl_xor_sync(0xffffffffu, s, o);
    if (lane == 0) out[w] = 1.f / (1.f + __expf(-s));
}

// ---------------- host launch ----------------
extern "C" void kernel_launch(void* const* d_in, const int* in_sizes, int n_in,
                              void* d_out, int out_size) {
    const float* x        = (const float*)d_in[0];
    const int*   eidx     = (const int*)d_in[1];
    const int*   head     = (const int*)d_in[2];
    const int*   rel      = (const int*)d_in[3];
    const int*   tail     = (const int*)d_in[4];
    const int*   g2l      = (const int*)d_in[5];
    const int*   reledge  = (const int*)d_in[6];
    const int*   simnb    = (const int*)d_in[7];
    const float* simw     = (const float*)d_in[8];
    const float* W1       = (const float*)d_in[9];
    const float* a1s      = (const float*)d_in[10];
    const float* a1d      = (const float*)d_in[11];
    const float* b1       = (const float*)d_in[12];
    const float* W2       = (const float*)d_in[13];
    const float* a2s      = (const float*)d_in[14];
    const float* a2d      = (const float*)d_in[15];
    const float* b2       = (const float*)d_in[16];
    const float* rel_emb  = (const float*)d_in[17];
    float* out = (float*)d_out;

    const int* src = eidx;
    const int* dst = eidx + EE;

    static cudaStream_t s2 = nullptr;
    static cudaEvent_t evFork = nullptr, evJoin = nullptr, evScan = nullptr, evTail = nullptr;
    if (s2 == nullptr) {
        cudaStreamCreateWithFlags(&s2, cudaStreamNonBlocking);
        cudaEventCreateWithFlags(&evFork, cudaEventDisableTiming);
        cudaEventCreateWithFlags(&evJoin, cudaEventDisableTiming);
        cudaEventCreateWithFlags(&evScan, cudaEventDisableTiming);
        cudaEventCreateWithFlags(&evTail, cudaEventDisableTiming);
    }

    cudaFuncSetAttribute(gemm_tc<1>, cudaFuncAttributeMaxDynamicSharedMemorySize, SMEM_GEMM);
    cudaFuncSetAttribute(gemm_tc<2>, cudaFuncAttributeMaxDynamicSharedMemorySize, SMEM_GEMM);

    dim3 ggrid((NN + BM - 1) / BM, 2);
    int nwBlocks = (NN * 32 + 255) / 256;

    // ---- fork: CSR build chain on s2, prep+gemm1 on main ----
    cudaEventRecord(evFork, 0);
    cudaStreamWaitEvent(s2, evFork, 0);

    hist_kernel<<<(EE + 255) / 256, 256, 0, s2>>>(dst, reledge);
    partial_kernel<<<PB, 256, 0, s2>>>();
    rowptr_kernel<<<PB, 512, 0, s2>>>();
    scatter_kernel<<<(EE + 255) / 256, 256, 0, s2>>>(src, dst);
    cudaEventRecord(evJoin, s2);

    prep_all_kernel<<<(NN * HD + 255) / 256, 256>>>(x, W1, W2);
    gemm_tc<1><<<ggrid, 256, SMEM_GEMM>>>(a1s, a1d, NN);

    // ---- join: aggregate needs CSR + gemm1 ----
    cudaStreamWaitEvent(0, evJoin, 0);
    gat_aggregate_kernel<1><<<nwBlocks, 256>>>(b1);
    gemm_tc<2><<<ggrid, 256, SMEM_GEMM>>>(a2s, a2d, NN);
    gat_aggregate_kernel<2><<<nwBlocks, 256>>>(b2);
    scan_seq_kernel<<<1, 256>>>(head, rel, g2l, simnb, simw);

    // ---- tail_zero overlaps decode ----
    cudaEventRecord(evScan, 0);
    cudaStreamWaitEvent(s2, evScan, 0);
    tail_zero_kernel<<<(NN + 255) / 256, 256, 0, s2>>>();
    cudaEventRecord(evTail, s2);

    decode_kernel<<<(BB * 32 + 255) / 256, 256>>>(head, rel, tail, rel_emb, out);
    cudaStreamWaitEvent(0, evTail, 0);
}